// round 15
// baseline (speedup 1.0000x reference)
#include <cuda_runtime.h>
#include <cuda_bf16.h>
#include <cstdint>

// AFM forward, tensor-core formulation v2.
// Build Inner[576,16] bf16 in smem ONCE, load A frags via ldmatrix.m8n8.x4,
// D = Inner @ [attn_W | fc_w | pad] via mma.sync.m16n8k16 (5 n-tiles).
// Epilogue on D frags; block softmax over 276 pairs per sample.
// cross term = (sum_p e^{s_p} g_p) / (sum_p e^{s_p})

#define NF 24
#define NE 16
#define NA 32
#define NP 276
#define NS 2
#define PPS 288            // padded pairs per sample (18 tiles of 16)
#define ROWS (NS*PPS)      // 576
#define NTILES (ROWS/16)   // 36
#define NWARP 4
#define NTHREADS 128
#define TPW (NTILES/NWARP) // 9 tiles per warp
#define EPAD 16            // emb row = 64B, float4-aligned
#define NWT 40             // W' cols: 32 W + 1 fcw + 7 zero

// pack two f32 -> bf16x2 (lo = first arg in low half)
__device__ __forceinline__ uint32_t bf16x2_of(float lo, float hi) {
    uint32_t d;
    asm("cvt.rn.bf16x2.f32 %0, %1, %2;" : "=r"(d) : "f"(hi), "f"(lo));
    return d;
}

__device__ __forceinline__ void mma_bf16(float d[4],
    uint32_t a0, uint32_t a1, uint32_t a2, uint32_t a3,
    uint32_t b0, uint32_t b1)
{
    asm volatile(
        "mma.sync.aligned.m16n8k16.row.col.f32.bf16.bf16.f32 "
        "{%0,%1,%2,%3}, {%4,%5,%6,%7}, {%8,%9}, {%0,%1,%2,%3};"
        : "+f"(d[0]), "+f"(d[1]), "+f"(d[2]), "+f"(d[3])
        : "r"(a0), "r"(a1), "r"(a2), "r"(a3), "r"(b0), "r"(b1));
}

__device__ __forceinline__ void ldsm_x4(uint32_t& a0, uint32_t& a1,
                                        uint32_t& a2, uint32_t& a3, uint32_t addr)
{
    asm volatile("ldmatrix.sync.aligned.m8n8.x4.shared.b16 {%0,%1,%2,%3}, [%4];"
        : "=r"(a0), "=r"(a1), "=r"(a2), "=r"(a3) : "r"(addr));
}

__global__ __launch_bounds__(NTHREADS) void afm_kernel(
    const int* __restrict__ x_raw,            // [B,24] int32 OR int64 (auto-detect)
    const float* __restrict__ embed_table,    // [V,16]
    const float* __restrict__ linear_table,   // [V,1]
    const float* __restrict__ linear_bias,    // [1]
    const float* __restrict__ attn_W,         // [16,32]
    const float* __restrict__ attn_b,         // [32]
    const float* __restrict__ proj_w,         // [32,1]
    const float* __restrict__ proj_b,         // [1]
    const float* __restrict__ fc_w,           // [16,1]
    const float* __restrict__ fc_b,           // [1]
    float* __restrict__ out)                  // [B,1]
{
    __shared__ __align__(16) float s_emb[NS][NF][EPAD];           // 3 KB
    __shared__ __align__(16) __nv_bfloat16 s_inner[ROWS][16];     // 18 KB, 32B rows
    __shared__ __align__(16) __nv_bfloat16 s_Wt[NWT * NE];        // [n][k], 1.25 KB
    __shared__ __align__(4)  uchar2 s_pairs[PPS];
    __shared__ float s_score[ROWS];
    __shared__ float s_gv[ROWS];
    __shared__ float s_bias[NA];
    __shared__ float s_pw[NA];
    __shared__ int   s_gid[NS][NF];
    __shared__ float s_lin[NS][NF];
    __shared__ float s_scal[2];
    __shared__ float s_red[3][NS][NWARP];
    __shared__ float s_smax[NS];

    const int tid  = threadIdx.x;
    const int wid  = tid >> 5;
    const int lane = tid & 31;
    const int tig  = lane & 3;        // thread in quad (k-col group)
    const int grp  = lane >> 2;       // quad id = row-in-tile
    const long long b0 = (long long)blockIdx.x * NS;

    // dtype probe: int64 values < 50000 have zero high words at odd positions.
    const bool is64 = (x_raw[1] == 0) & (x_raw[3] == 0) & (x_raw[5] == 0) & (x_raw[7] == 0);

    // ---- stage indices + linear terms ----
    if (tid < NS * NF) {
        int s = tid / NF;
        int f = tid - s * NF;
        long long flat = (b0 + s) * NF + f;
        int xv = is64 ? x_raw[flat * 2] : x_raw[flat];
        int gid = xv + f * 50000;
        s_gid[s][f] = gid;
        s_lin[s][f] = linear_table[gid];
    }
    // W' transposed to [n][k] bf16: n<32 -> attn_W[k][n]; n==32 -> fc_w; else 0
    for (int t = tid; t < NWT * NE; t += NTHREADS) {
        int n = t / NE, k = t - n * NE;
        float v = (n < NA) ? attn_W[k * NA + n] : ((n == NA) ? fc_w[k] : 0.f);
        s_Wt[n * NE + k] = __float2bfloat16(v);
    }
    // pair LUT (padded entries -> (0,1), harmless)
    for (int p = tid; p < PPS; p += NTHREADS) {
        int r = 0, c = 1;
        if (p < NP) {
            int pp = p, base = 0;
            while (pp >= base + (NF - 1 - r)) { base += NF - 1 - r; r++; }
            c = r + 1 + (pp - base);
        }
        s_pairs[p] = make_uchar2((unsigned char)r, (unsigned char)c);
    }
    if (tid < NA) {
        s_bias[tid] = attn_b[tid];
        s_pw[tid]   = proj_w[tid];
    }
    if (tid == 0) {
        s_scal[0] = proj_b[0];
        s_scal[1] = fc_b[0] + linear_bias[0];
    }
    __syncthreads();

    // ---- gather embeddings as float4 (48 rows x 4 chunks) ----
    for (int t = tid; t < NS * NF * 4; t += NTHREADS) {
        int s = t / (NF * 4);
        int rem = t - s * (NF * 4);
        int f = rem >> 2, q = rem & 3;
        const float4* src = (const float4*)embed_table;
        ((float4*)&s_emb[s][f][0])[q] = src[(long long)s_gid[s][f] * 4 + q];
    }
    __syncthreads();

    // ---- build Inner[576][16] bf16 (each thread ~4.5 rows) ----
    for (int p = tid; p < ROWS; p += NTHREADS) {
        int s = (p >= PPS);
        int pp = p - s * PPS;
        uchar2 q = s_pairs[pp];
        const float4* ra = (const float4*)&s_emb[s][q.x][0];
        const float4* ca = (const float4*)&s_emb[s][q.y][0];
        float4 r0 = ra[0], r1 = ra[1], r2 = ra[2], r3 = ra[3];
        float4 c0 = ca[0], c1 = ca[1], c2 = ca[2], c3 = ca[3];
        uint4 w;
        w.x = bf16x2_of(r0.x*c0.x, r0.y*c0.y);
        w.y = bf16x2_of(r0.z*c0.z, r0.w*c0.w);
        w.z = bf16x2_of(r1.x*c1.x, r1.y*c1.y);
        w.w = bf16x2_of(r1.z*c1.z, r1.w*c1.w);
        *(uint4*)&s_inner[p][0] = w;
        uint4 v;
        v.x = bf16x2_of(r2.x*c2.x, r2.y*c2.y);
        v.y = bf16x2_of(r2.z*c2.z, r2.w*c2.w);
        v.z = bf16x2_of(r3.x*c3.x, r3.y*c3.y);
        v.w = bf16x2_of(r3.z*c3.z, r3.w*c3.w);
        *(uint4*)&s_inner[p][8] = v;
    }

    // ---- preload B fragments (5 n-tiles) + bias/proj for this lane's cols ----
    uint32_t bfr[5][2];
    {
        const uint32_t* wt32 = (const uint32_t*)s_Wt;
        #pragma unroll
        for (int t = 0; t < 5; t++) {
            int n = 8 * t + grp;
            bfr[t][0] = wt32[(n * NE + tig * 2) >> 1];
            bfr[t][1] = wt32[(n * NE + tig * 2 + 8) >> 1];
        }
    }
    float bias8[8], pw8[8];
    #pragma unroll
    for (int t = 0; t < 4; t++) {
        int c = 8 * t + tig * 2;
        bias8[2*t]   = s_bias[c];
        bias8[2*t+1] = s_bias[c + 1];
        pw8[2*t]     = s_pw[c];
        pw8[2*t+1]   = s_pw[c + 1];
    }
    __syncthreads();

    // ---- per-warp: 9 M-tiles via ldmatrix + 5 MMAs each ----
    {
        uint32_t inner_base = (uint32_t)__cvta_generic_to_shared(&s_inner[0][0]);
        int blk = lane >> 3, rib = lane & 7;
        // lane address: row = rib + (blk&1)*8, k-half = blk>>1 (16B offset)
        uint32_t aAddr = inner_base + (uint32_t)((rib + (blk & 1) * 8) * 32 + (blk >> 1) * 16);

        for (int i = 0; i < TPW; i++) {
            int m = wid * TPW + i;
            uint32_t a0, a1, a2, a3;
            ldsm_x4(a0, a1, a2, a3, aAddr + (uint32_t)m * 512u);

            float d[5][4];
            #pragma unroll
            for (int t = 0; t < 5; t++) {
                d[t][0] = d[t][1] = d[t][2] = d[t][3] = 0.f;
                mma_bf16(d[t], a0, a1, a2, a3, bfr[t][0], bfr[t][1]);
            }

            // epilogue: relu(d + bias) . projw per row; g from col 32
            float pa = 0.f, pbv = 0.f;
            #pragma unroll
            for (int t = 0; t < 4; t++) {
                pa  = fmaf(fmaxf(d[t][0] + bias8[2*t],     0.f), pw8[2*t],     pa);
                pa  = fmaf(fmaxf(d[t][1] + bias8[2*t + 1], 0.f), pw8[2*t + 1], pa);
                pbv = fmaf(fmaxf(d[t][2] + bias8[2*t],     0.f), pw8[2*t],     pbv);
                pbv = fmaf(fmaxf(d[t][3] + bias8[2*t + 1], 0.f), pw8[2*t + 1], pbv);
            }
            float ga = (tig == 0) ? d[4][0] : 0.f;
            float gb = (tig == 0) ? d[4][2] : 0.f;

            pa  += __shfl_xor_sync(0xffffffffu, pa, 1);  pa  += __shfl_xor_sync(0xffffffffu, pa, 2);
            pbv += __shfl_xor_sync(0xffffffffu, pbv, 1); pbv += __shfl_xor_sync(0xffffffffu, pbv, 2);
            ga  += __shfl_xor_sync(0xffffffffu, ga, 1);  ga  += __shfl_xor_sync(0xffffffffu, ga, 2);
            gb  += __shfl_xor_sync(0xffffffffu, gb, 1);  gb  += __shfl_xor_sync(0xffffffffu, gb, 2);

            if (tig == 0) {
                int rbase = m * 16 + grp;
                s_score[rbase]     = pa  + s_scal[0];
                s_score[rbase + 8] = pbv + s_scal[0];
                s_gv[rbase]     = ga;
                s_gv[rbase + 8] = gb;
            }
        }
    }
    __syncthreads();

    // ---- block softmax over 276 pairs, both samples ----
    float mx0 = -1e30f, mx1 = -1e30f;
    for (int p = tid; p < NP; p += NTHREADS) {
        mx0 = fmaxf(mx0, s_score[p]);
        mx1 = fmaxf(mx1, s_score[PPS + p]);
    }
    #pragma unroll
    for (int o = 16; o > 0; o >>= 1) {
        mx0 = fmaxf(mx0, __shfl_xor_sync(0xffffffffu, mx0, o));
        mx1 = fmaxf(mx1, __shfl_xor_sync(0xffffffffu, mx1, o));
    }
    if (lane == 0) { s_red[0][0][wid] = mx0; s_red[0][1][wid] = mx1; }
    __syncthreads();
    if (tid == 0) {
        float a = s_red[0][0][0], b = s_red[0][1][0];
        #pragma unroll
        for (int w = 1; w < NWARP; w++) {
            a = fmaxf(a, s_red[0][0][w]);
            b = fmaxf(b, s_red[0][1][w]);
        }
        s_smax[0] = a; s_smax[1] = b;
    }
    __syncthreads();

    const float sm0 = s_smax[0], sm1 = s_smax[1];
    float se0 = 0.f, sg0 = 0.f, se1 = 0.f, sg1 = 0.f;
    for (int p = tid; p < NP; p += NTHREADS) {
        float e0 = __expf(s_score[p] - sm0);
        float e1 = __expf(s_score[PPS + p] - sm1);
        se0 += e0; sg0 += e0 * s_gv[p];
        se1 += e1; sg1 += e1 * s_gv[PPS + p];
    }
    #pragma unroll
    for (int o = 16; o > 0; o >>= 1) {
        se0 += __shfl_xor_sync(0xffffffffu, se0, o);
        sg0 += __shfl_xor_sync(0xffffffffu, sg0, o);
        se1 += __shfl_xor_sync(0xffffffffu, se1, o);
        sg1 += __shfl_xor_sync(0xffffffffu, sg1, o);
    }
    if (lane == 0) {
        s_red[1][0][wid] = se0; s_red[2][0][wid] = sg0;
        s_red[1][1][wid] = se1; s_red[2][1][wid] = sg1;
    }
    __syncthreads();

    if (tid < NS) {
        int s = tid;
        float tse = 0.f, tsg = 0.f;
        #pragma unroll
        for (int w = 0; w < NWARP; w++) { tse += s_red[1][s][w]; tsg += s_red[2][s][w]; }
        float lin = 0.f;
        #pragma unroll
        for (int f = 0; f < NF; f++) lin += s_lin[s][f];
        out[b0 + s] = lin + s_scal[1] + tsg / tse;
    }
}

extern "C" void kernel_launch(void* const* d_in, const int* in_sizes, int n_in,
                              void* d_out, int out_size) {
    const int* x              = (const int*)d_in[0];
    const float* embed_table  = (const float*)d_in[1];
    const float* linear_table = (const float*)d_in[2];
    const float* linear_bias  = (const float*)d_in[3];
    const float* attn_W       = (const float*)d_in[4];
    const float* attn_b       = (const float*)d_in[5];
    const float* proj_w       = (const float*)d_in[6];
    const float* proj_b       = (const float*)d_in[7];
    const float* fc_w         = (const float*)d_in[8];
    const float* fc_b         = (const float*)d_in[9];
    float* out = (float*)d_out;

    int B = out_size;                 // one output per sample
    int nblocks = (B + NS - 1) / NS;  // 16384 -> 8192
    afm_kernel<<<nblocks, NTHREADS>>>(x, embed_table, linear_table, linear_bias,
                                      attn_W, attn_b, proj_w, proj_b, fc_w, fc_b, out);
}

// round 16
// speedup vs baseline: 1.4743x; 1.4743x over previous
#include <cuda_runtime.h>
#include <cuda_bf16.h>
#include <cstdint>

// AFM forward, tensor-core formulation v3 (R14 + k-permutation float4 loads,
// bias-in-accumulator, packed pair LUT, EPAD=20).
// Per CTA: 2 samples. Inner rows built in-register as bf16 MMA A-frags with a
// permuted k mapping (sigma) so each lane loads one float4 per emb row.
// D = Inner @ [attn_W | fc_w | pad] via mma.sync.m16n8k16 (5 n-tiles).
// cross term = (sum_p e^{s_p} g_p) / (sum_p e^{s_p})

#define NF 24
#define NE 16
#define NA 32
#define NP 276
#define NS 2
#define PPS 288            // padded pairs per sample (18 tiles of 16)
#define ROWS (NS*PPS)      // 576
#define NTILES (ROWS/16)   // 36
#define NWARP 4
#define NTHREADS 128
#define TPW (NTILES/NWARP) // 9 tiles per warp
#define EPAD 20            // emb row = 80B (float4-aligned, 8 distinct bank groups)
#define NWT 40             // W' cols: 32 W + 1 fcw + 7 zero

// sigma: fragment k-position -> actual column
// pos 2t,2t+1 (t=tig) -> col 4t,4t+1 ; pos 2t+8,2t+9 -> col 4t+2,4t+3
__host__ __device__ __forceinline__ int sigma_k(int k) {
    return (k < 8) ? ((k >> 1) * 4 + (k & 1))
                   : (((k - 8) >> 1) * 4 + 2 + (k & 1));
}

// pack two f32 -> bf16x2 (lo = first arg in low half)
__device__ __forceinline__ uint32_t bf16x2_of(float lo, float hi) {
    uint32_t d;
    asm("cvt.rn.bf16x2.f32 %0, %1, %2;" : "=r"(d) : "f"(hi), "f"(lo));
    return d;
}

__device__ __forceinline__ void mma_bf16(float d[4],
    uint32_t a0, uint32_t a1, uint32_t a2, uint32_t a3,
    uint32_t b0, uint32_t b1)
{
    asm volatile(
        "mma.sync.aligned.m16n8k16.row.col.f32.bf16.bf16.f32 "
        "{%0,%1,%2,%3}, {%4,%5,%6,%7}, {%8,%9}, {%0,%1,%2,%3};"
        : "+f"(d[0]), "+f"(d[1]), "+f"(d[2]), "+f"(d[3])
        : "r"(a0), "r"(a1), "r"(a2), "r"(a3), "r"(b0), "r"(b1));
}

__global__ __launch_bounds__(NTHREADS) void afm_kernel(
    const int* __restrict__ x_raw,            // [B,24] int32 OR int64 (auto-detect)
    const float* __restrict__ embed_table,    // [V,16]
    const float* __restrict__ linear_table,   // [V,1]
    const float* __restrict__ linear_bias,    // [1]
    const float* __restrict__ attn_W,         // [16,32]
    const float* __restrict__ attn_b,         // [32]
    const float* __restrict__ proj_w,         // [32,1]
    const float* __restrict__ proj_b,         // [1]
    const float* __restrict__ fc_w,           // [16,1]
    const float* __restrict__ fc_b,           // [1]
    float* __restrict__ out)                  // [B,1]
{
    __shared__ __align__(16) float s_emb[NS][NF][EPAD];          // 3.75 KB
    __shared__ __align__(16) __nv_bfloat16 s_Wt[NWT * NE];       // [n][k-pos], 1.25 KB
    __shared__ __align__(4)  uchar4 s_p4[NTILES * 8];            // (rA,cA,rB,cB) per (tile,row)
    __shared__ float s_score[ROWS];
    __shared__ float s_gv[ROWS];
    __shared__ float s_bias[NA];
    __shared__ float s_pw[NA];
    __shared__ int   s_gid[NS][NF];
    __shared__ float s_lin[NS][NF];
    __shared__ float s_scal[2];
    __shared__ float s_red[3][NS][NWARP];
    __shared__ float s_smax[NS];

    const int tid  = threadIdx.x;
    const int wid  = tid >> 5;
    const int lane = tid & 31;
    const int tig  = lane & 3;        // thread in quad (k group)
    const int grp  = lane >> 2;       // quad id = row-in-tile
    const long long b0 = (long long)blockIdx.x * NS;

    // dtype probe: int64 values < 50000 have zero high words at odd positions.
    const bool is64 = (x_raw[1] == 0) & (x_raw[3] == 0) & (x_raw[5] == 0) & (x_raw[7] == 0);

    // ---- stage indices + linear terms ----
    if (tid < NS * NF) {
        int s = tid / NF;
        int f = tid - s * NF;
        long long flat = (b0 + s) * NF + f;
        int xv = is64 ? x_raw[flat * 2] : x_raw[flat];
        int gid = xv + f * 50000;
        s_gid[s][f] = gid;
        s_lin[s][f] = linear_table[gid];
    }
    // W' at [n][k-pos] with permuted k: value = W'[sigma(k)][n]
    for (int t = tid; t < NWT * NE; t += NTHREADS) {
        int n = t / NE, k = t - n * NE;
        int ks = sigma_k(k);
        float v = (n < NA) ? attn_W[ks * NA + n] : ((n == NA) ? fc_w[ks] : 0.f);
        s_Wt[n * NE + k] = __float2bfloat16(v);
    }
    // packed pair LUT: entry (m, g) = pairs for rows m*16+g and m*16+g+8
    for (int t = tid; t < NTILES * 8; t += NTHREADS) {
        int m = t >> 3, g = t & 7;
        int smp = (m >= NTILES / 2);
        int pb = (m - smp * (NTILES / 2)) * 16;
        int rr[2], cc[2];
        #pragma unroll
        for (int h = 0; h < 2; h++) {
            int p = pb + g + h * 8;
            int r = 0, c = 1;
            if (p < NP) {
                int pp = p, base = 0;
                while (pp >= base + (NF - 1 - r)) { base += NF - 1 - r; r++; }
                c = r + 1 + (pp - base);
            }
            rr[h] = r; cc[h] = c;
        }
        s_p4[t] = make_uchar4((unsigned char)rr[0], (unsigned char)cc[0],
                              (unsigned char)rr[1], (unsigned char)cc[1]);
    }
    if (tid < NA) {
        s_bias[tid] = attn_b[tid];
        s_pw[tid]   = proj_w[tid];
    }
    if (tid == 0) {
        s_scal[0] = proj_b[0];
        s_scal[1] = fc_b[0] + linear_bias[0];
    }
    __syncthreads();

    // ---- gather embeddings as float4 (48 rows x 4 chunks) ----
    for (int t = tid; t < NS * NF * 4; t += NTHREADS) {
        int s = t / (NF * 4);
        int rem = t - s * (NF * 4);
        int f = rem >> 2, q = rem & 3;
        const float4* src = (const float4*)embed_table;
        ((float4*)&s_emb[s][f][0])[q] = src[(long long)s_gid[s][f] * 4 + q];
    }
    __syncthreads();

    // ---- preload B fragments (5 n-tiles) + bias/proj for this lane's cols ----
    uint32_t bfr[5][2];
    {
        const uint32_t* wt32 = (const uint32_t*)s_Wt;
        #pragma unroll
        for (int t = 0; t < 5; t++) {
            int n = 8 * t + grp;
            bfr[t][0] = wt32[(n * NE + tig * 2) >> 1];
            bfr[t][1] = wt32[(n * NE + tig * 2 + 8) >> 1];
        }
    }
    float bias8[8], pw8[8];
    #pragma unroll
    for (int t = 0; t < 4; t++) {
        int c = 8 * t + tig * 2;
        bias8[2*t]   = s_bias[c];
        bias8[2*t+1] = s_bias[c + 1];
        pw8[2*t]     = s_pw[c];
        pw8[2*t+1]   = s_pw[c + 1];
    }

    // ---- per-warp: 9 M-tiles ----
    {
        // warps 0,1 -> sample 0 ; warps 2,3 -> sample 1 (m ranges don't straddle)
        const float* eb = &s_emb[wid >> 1][0][0];
        const int coff = tig * 4;

        for (int i = 0; i < TPW; i++) {
            int m = wid * TPW + i;
            uchar4 q = s_p4[m * 8 + grp];

            // row grp: pair (q.x,q.y); row grp+8: pair (q.z,q.w)
            float4 ra = *(const float4*)(eb + (int)q.x * EPAD + coff);
            float4 ca = *(const float4*)(eb + (int)q.y * EPAD + coff);
            float4 rb = *(const float4*)(eb + (int)q.z * EPAD + coff);
            float4 cb = *(const float4*)(eb + (int)q.w * EPAD + coff);
            float4 pA = make_float4(ra.x*ca.x, ra.y*ca.y, ra.z*ca.z, ra.w*ca.w);
            float4 pB = make_float4(rb.x*cb.x, rb.y*cb.y, rb.z*cb.z, rb.w*cb.w);
            // sigma: slots {2t,2t+1}->cols{4t,4t+1} (a0/a1), {2t+8,2t+9}->cols{4t+2,4t+3} (a2/a3)
            uint32_t a0 = bf16x2_of(pA.x, pA.y);
            uint32_t a1 = bf16x2_of(pB.x, pB.y);
            uint32_t a2 = bf16x2_of(pA.z, pA.w);
            uint32_t a3 = bf16x2_of(pB.z, pB.w);

            float d[5][4];
            #pragma unroll
            for (int t = 0; t < 4; t++) {
                d[t][0] = bias8[2*t]; d[t][1] = bias8[2*t+1];
                d[t][2] = bias8[2*t]; d[t][3] = bias8[2*t+1];
            }
            d[4][0] = d[4][1] = d[4][2] = d[4][3] = 0.f;
            #pragma unroll
            for (int t = 0; t < 5; t++)
                mma_bf16(d[t], a0, a1, a2, a3, bfr[t][0], bfr[t][1]);

            // epilogue: h already includes bias; score = relu(h).projw (+proj_b at store)
            float pa = 0.f, pbv = 0.f;
            #pragma unroll
            for (int t = 0; t < 4; t++) {
                pa  = fmaf(fmaxf(d[t][0], 0.f), pw8[2*t],     pa);
                pa  = fmaf(fmaxf(d[t][1], 0.f), pw8[2*t + 1], pa);
                pbv = fmaf(fmaxf(d[t][2], 0.f), pw8[2*t],     pbv);
                pbv = fmaf(fmaxf(d[t][3], 0.f), pw8[2*t + 1], pbv);
            }
            pa  += __shfl_xor_sync(0xffffffffu, pa, 1);  pa  += __shfl_xor_sync(0xffffffffu, pa, 2);
            pbv += __shfl_xor_sync(0xffffffffu, pbv, 1); pbv += __shfl_xor_sync(0xffffffffu, pbv, 2);

            if (tig == 0) {
                // g (col 32) lives on tig==0: d[4][0] (row grp), d[4][2] (row grp+8)
                int rbase = m * 16 + grp;
                s_score[rbase]     = pa  + s_scal[0];
                s_score[rbase + 8] = pbv + s_scal[0];
                s_gv[rbase]     = d[4][0];
                s_gv[rbase + 8] = d[4][2];
            }
        }
    }
    __syncthreads();

    // ---- block softmax over 276 pairs, both samples ----
    float mx0 = -1e30f, mx1 = -1e30f;
    for (int p = tid; p < NP; p += NTHREADS) {
        mx0 = fmaxf(mx0, s_score[p]);
        mx1 = fmaxf(mx1, s_score[PPS + p]);
    }
    #pragma unroll
    for (int o = 16; o > 0; o >>= 1) {
        mx0 = fmaxf(mx0, __shfl_xor_sync(0xffffffffu, mx0, o));
        mx1 = fmaxf(mx1, __shfl_xor_sync(0xffffffffu, mx1, o));
    }
    if (lane == 0) { s_red[0][0][wid] = mx0; s_red[0][1][wid] = mx1; }
    __syncthreads();
    if (tid == 0) {
        float a = s_red[0][0][0], b = s_red[0][1][0];
        #pragma unroll
        for (int w = 1; w < NWARP; w++) {
            a = fmaxf(a, s_red[0][0][w]);
            b = fmaxf(b, s_red[0][1][w]);
        }
        s_smax[0] = a; s_smax[1] = b;
    }
    __syncthreads();

    const float sm0 = s_smax[0], sm1 = s_smax[1];
    float se0 = 0.f, sg0 = 0.f, se1 = 0.f, sg1 = 0.f;
    for (int p = tid; p < NP; p += NTHREADS) {
        float e0 = __expf(s_score[p] - sm0);
        float e1 = __expf(s_score[PPS + p] - sm1);
        se0 += e0; sg0 += e0 * s_gv[p];
        se1 += e1; sg1 += e1 * s_gv[PPS + p];
    }
    #pragma unroll
    for (int o = 16; o > 0; o >>= 1) {
        se0 += __shfl_xor_sync(0xffffffffu, se0, o);
        sg0 += __shfl_xor_sync(0xffffffffu, sg0, o);
        se1 += __shfl_xor_sync(0xffffffffu, se1, o);
        sg1 += __shfl_xor_sync(0xffffffffu, sg1, o);
    }
    if (lane == 0) {
        s_red[1][0][wid] = se0; s_red[2][0][wid] = sg0;
        s_red[1][1][wid] = se1; s_red[2][1][wid] = sg1;
    }
    __syncthreads();

    if (tid < NS) {
        int s = tid;
        float tse = 0.f, tsg = 0.f;
        #pragma unroll
        for (int w = 0; w < NWARP; w++) { tse += s_red[1][s][w]; tsg += s_red[2][s][w]; }
        float lin = 0.f;
        #pragma unroll
        for (int f = 0; f < NF; f++) lin += s_lin[s][f];
        out[b0 + s] = lin + s_scal[1] + tsg / tse;
    }
}

extern "C" void kernel_launch(void* const* d_in, const int* in_sizes, int n_in,
                              void* d_out, int out_size) {
    const int* x              = (const int*)d_in[0];
    const float* embed_table  = (const float*)d_in[1];
    const float* linear_table = (const float*)d_in[2];
    const float* linear_bias  = (const float*)d_in[3];
    const float* attn_W       = (const float*)d_in[4];
    const float* attn_b       = (const float*)d_in[5];
    const float* proj_w       = (const float*)d_in[6];
    const float* proj_b       = (const float*)d_in[7];
    const float* fc_w         = (const float*)d_in[8];
    const float* fc_b         = (const float*)d_in[9];
    float* out = (float*)d_out;

    int B = out_size;                 // one output per sample
    int nblocks = (B + NS - 1) / NS;  // 16384 -> 8192
    afm_kernel<<<nblocks, NTHREADS>>>(x, embed_table, linear_table, linear_bias,
                                      attn_W, attn_b, proj_w, proj_b, fc_w, fc_b, out);
}